// round 1
// baseline (speedup 1.0000x reference)
#include <cuda_runtime.h>

// WaveletTransformLayer: x (B=128, T=2048, F=32) fp32.
// Per (b,f) series: 3-level moving-average pyramid (w = 2, 4, 8),
// details + final approx concatenated, / T, per-series contiguous in output.

constexpr int B = 128;
constexpr int T = 2048;
constexpr int F = 32;

constexpr int N1 = T - 2 + 1;        // 2047
constexpr int N2 = N1 - 4 + 1;       // 2044
constexpr int N3 = N2 - 8 + 1;       // 2037
constexpr int OUT_PER = N1 + N2 + N3 + N3;  // 8165

__global__ __launch_bounds__(256, 8)
void wavelet_kernel(const float* __restrict__ x, float* __restrict__ out) {
    __shared__ float sa[T];
    __shared__ float sb[T];

    const int series = blockIdx.x;          // = b * F + f
    const int bb = series >> 5;             // / F
    const int f  = series & (F - 1);        // % F

    const float* xp = x + (size_t)bb * T * F + f;
    float* op = out + (size_t)series * OUT_PER;
    const float invT = 1.0f / (float)T;

    // Load series (strided gather; input fits in L2, re-read across the 32
    // sibling blocks of the same b hits L2 not DRAM).
    #pragma unroll
    for (int t = threadIdx.x; t < T; t += 256)
        sa[t] = xp[(size_t)t * F];
    __syncthreads();

    // Level 1: w = 2.  ma1[i] = (a[i]+a[i+1])/2, detail = a[i+1]-ma1.
    #pragma unroll
    for (int i = threadIdx.x; i < N1; i += 256) {
        float a0 = sa[i], a1 = sa[i + 1];
        float ma = (a0 + a1) * 0.5f;
        op[i] = (a1 - ma) * invT;
        sb[i] = ma;
    }
    __syncthreads();

    // Level 2: w = 4 over sb[0..N1).
    #pragma unroll
    for (int i = threadIdx.x; i < N2; i += 256) {
        float s = sb[i] + sb[i + 1] + sb[i + 2] + sb[i + 3];
        float ma = s * 0.25f;
        op[N1 + i] = (sb[i + 3] - ma) * invT;
        sa[i] = ma;  // reuse sa; input values no longer needed
    }
    __syncthreads();

    // Level 3: w = 8 over sa[0..N2). Emit detail and final approx.
    #pragma unroll
    for (int i = threadIdx.x; i < N3; i += 256) {
        float s = sa[i]     + sa[i + 1] + sa[i + 2] + sa[i + 3]
                + sa[i + 4] + sa[i + 5] + sa[i + 6] + sa[i + 7];
        float ma = s * 0.125f;
        op[N1 + N2 + i]      = (sa[i + 7] - ma) * invT;
        op[N1 + N2 + N3 + i] = ma * invT;
    }
}

extern "C" void kernel_launch(void* const* d_in, const int* in_sizes, int n_in,
                              void* d_out, int out_size) {
    const float* x = (const float*)d_in[0];
    float* out = (float*)d_out;
    wavelet_kernel<<<B * F, 256>>>(x, out);
}